// round 17
// baseline (speedup 1.0000x reference)
#include <cuda_runtime.h>
#include <cuda_bf16.h>
#include <cuda_fp16.h>
#include <cstdint>

// B=2, S=1024, D=1024, H=16, KVH=4, HD=64, TOT=1536
// QKV projection: fp16 mma, 2-term (x split [hi|lo] exactly; W single fp16).
// Attention (QK, PV) + output projection: single-term fp16 mma.
// Flash attention: 128-thread CTAs (64 q-rows), occ 2/SM so softmax overlaps
// mma across CTAs; 2 K slots + single V buffer cp.async pipeline.

typedef unsigned long long ull;
typedef long long ll;
#define DEVFN static __device__ __forceinline__

// ---------------- PTX helpers ----------------
DEVFN uint32_t smem_u32(const void* p){
  uint32_t a; asm("{ .reg .u64 t; cvta.to.shared.u64 t, %1; cvt.u32.u64 %0, t; }":"=r"(a):"l"(p)); return a;
}
DEVFN void ldsm_x4(uint32_t* r, uint32_t addr){
  asm volatile("ldmatrix.sync.aligned.m8n8.x4.shared.b16 {%0,%1,%2,%3}, [%4];"
    : "=r"(r[0]),"=r"(r[1]),"=r"(r[2]),"=r"(r[3]) : "r"(addr));
}
DEVFN void mma16816h(float* c, const uint32_t* a, const uint32_t* b){
  asm volatile("mma.sync.aligned.m16n8k16.row.col.f32.f16.f16.f32 "
    "{%0,%1,%2,%3}, {%4,%5,%6,%7}, {%8,%9}, {%0,%1,%2,%3};"
    : "+f"(c[0]),"+f"(c[1]),"+f"(c[2]),"+f"(c[3])
    : "r"(a[0]),"r"(a[1]),"r"(a[2]),"r"(a[3]), "r"(b[0]),"r"(b[1]));
}
DEVFN void cp_async16(uint32_t dst, const void* src){
  asm volatile("cp.async.cg.shared.global [%0], [%1], 16;" :: "r"(dst), "l"(src));
}
#define CP_COMMIT() asm volatile("cp.async.commit_group;" ::: "memory")
template<int N> DEVFN void cp_waitg(){ asm volatile("cp.async.wait_group %0;"::"n"(N):"memory"); }

DEVFN uint32_t packh2(float a, float b){
  __half2 t = __floats2half2_rn(a, b); return *(uint32_t*)&t;
}
DEVFN void hsplit(float x, __half &hi, __half &lo){
  hi = __float2half_rn(x);
  lo = __float2half_rn(x - __half2float(hi));
}
DEVFN uint32_t packhh(__half a, __half b){
  __half2 t(a, b); return *(uint32_t*)&t;
}

// ---------------- scratch (device globals) ----------------
__device__ __align__(128) __half g_x_pack   [2u*2048u*2048u];  // [lc|gc], rows [hi|lo] fp16
__device__ __align__(128) __half g_wqkv_pack[2u*1536u*1024u];  // fp16 single plane
__device__ __align__(128) __half g_wpr_pack [2u*1024u*2048u];  // fp16 single plane
__device__ __align__(128) float g_comb[2u*2048u*1536u];
__device__ __align__(128) __half g_q  [32u*1024u*128u];        // q*log2e/8, fp16
__device__ __align__(128) __half g_k  [8u*1024u*128u];         // fp16
__device__ __align__(128) __half g_vT [8u*128u*1024u];         // V^T fp16
__device__ __align__(128) __half g_ao [2048u*2048u];           // attn-out fp16
__device__ __align__(128) float g_yy[4096u*1024u];

// ---------------- merged pack ----------------
// blocks: [0,1024) xl split | [1024,2048) xg split | [2048,2816) wlc single
//         [2816,3584) wgc single | [3584,4608) wlo single | [4608,5632) wgo single
__global__ __launch_bounds__(256)
void packAll(const float* __restrict__ xl, const float* __restrict__ xg,
             const float* __restrict__ wlc, const float* __restrict__ wgc,
             const float* __restrict__ wlo, const float* __restrict__ wgo,
             __half* __restrict__ xp, __half* __restrict__ wq,
             __half* __restrict__ wp)
{
  int bx = blockIdx.x;
  if (bx >= 2048){
    const float* src; __half* dst;
    if (bx < 3584){
      bx -= 2048;
      if (bx < 768){ src = wlc; dst = wq; }
      else { src = wgc; dst = wq + 1536u*1024u; bx -= 768; }
    } else {
      bx -= 3584;
      if (bx < 1024){ src = wlo; dst = wp; }
      else { src = wgo; dst = wp + 1024u*2048u; bx -= 1024; }
    }
    int idx = (bx*256 + threadIdx.x)*8;
    float4 v0 = *(const float4*)(src + idx);
    float4 v1 = *(const float4*)(src + idx + 4);
    uint4 hv = make_uint4(packh2(v0.x,v0.y), packh2(v0.z,v0.w),
                          packh2(v1.x,v1.y), packh2(v1.z,v1.w));
    *(uint4*)(dst + idx) = hv;
    return;
  }
  const float* src; __half* dst;
  if (bx < 1024){ src = xl; dst = xp; }
  else { src = xg; dst = xp + 2048u*2048u; bx -= 1024; }
  int idx = (bx*256 + threadIdx.x)*8;
  float4 v0 = *(const float4*)(src + idx);
  float4 v1 = *(const float4*)(src + idx + 4);
  int r = idx >> 10, k = idx & 1023;
  __half* d = dst + (ll)r*2048 + k;
  float vv[8] = {v0.x,v0.y,v0.z,v0.w,v1.x,v1.y,v1.z,v1.w};
  uint32_t hw[4], lw[4];
#pragma unroll
  for (int i=0;i<4;i++){
    __half h0,l0,h1,l1;
    hsplit(vv[2*i],h0,l0); hsplit(vv[2*i+1],h1,l1);
    hw[i] = packhh(h0,h1); lw[i] = packhh(l0,l1);
  }
  *(uint4*)(d)        = make_uint4(hw[0],hw[1],hw[2],hw[3]);
  *(uint4*)(d + 1024) = make_uint4(lw[0],lw[1],lw[2],lw[3]);
}

// ---------------- mma.sync GEMM template (fp16) ----------------
#define ROWB2 144

template<bool SPLIT_N, int NT8, int TERMS>
__global__ __launch_bounds__(256, 2)
void gemm_mma(const __half* __restrict__ A, const __half* __restrict__ B,
              float* __restrict__ Cf,
              const float* __restrict__ bias0, const float* __restrict__ bias1,
              int Kreal, int lgn1, int lda, int ldb, int ldc,
              ll sA, ll sB, ll sC, float cscale)
{
  constexpr int NP    = NT8/2;
  constexpr int BROWS = NT8*16;
  constexpr int BIT   = NT8/2;
  constexpr int STGT  = (128 + BROWS)*ROWB2;

  extern __shared__ char smem[];
  const uint32_t sb = smem_u32(smem);
  const int tid = threadIdx.x, wid = tid>>5, lane = tid&31;
  const int z = blockIdx.z;
  const int m0 = blockIdx.y*128, n0 = blockIdx.x*(NT8*16);
  A += z*sA + (ll)m0*lda;
  B += z*sB + (ll)n0*ldb;
  Cf += z*sC;

  const int wm = wid>>1, wn = wid&1;
  const int n1m = (1<<lgn1) - 1;

  float acc[2][NT8][4];
#pragma unroll
  for (int i=0;i<2;i++)
#pragma unroll
    for (int j=0;j<NT8;j++)
#pragma unroll
      for (int q=0;q<4;q++) acc[i][j][q]=0.f;

  const int nch = TERMS << lgn1;

  auto loadStage = [&](int c, int s){
    int t = c >> lgn1, r = c & n1m;
    int acol = ((t==1) ? Kreal : 0) + r*64;
    int bcol = ((t==2) ? Kreal : 0) + r*64;
    const __half* Ak = A + acol;
    const __half* Bk = B + bcol;
    uint32_t abase = sb + s*STGT;
    uint32_t bbase = abase + 128*ROWB2;
#pragma unroll
    for (int i=0;i<4;i++){
      int f = tid + i*256;
      int rr = f>>3, q = f&7;
      cp_async16(abase + rr*ROWB2 + q*16, (const char*)(Ak + (ll)rr*lda) + q*16);
    }
#pragma unroll
    for (int i=0;i<BIT;i++){
      int f = tid + i*256;
      int rr = f>>3, q = f&7;
      cp_async16(bbase + rr*ROWB2 + q*16, (const char*)(Bk + (ll)rr*ldb) + q*16);
    }
  };

  loadStage(0, 0); CP_COMMIT();
  loadStage(1, 1); CP_COMMIT();

  for (int c=0; c<nch; c++){
    cp_waitg<1>();
    __syncthreads();
    if (c+2 < nch) loadStage(c+2, (c+2)%3);
    CP_COMMIT();

    const uint32_t abase = sb + (c%3)*STGT;
    const uint32_t bbase = abase + 128*ROWB2;
#pragma unroll
    for (int kk=0; kk<64; kk+=16){
      uint32_t a[2][4], b[NP][4];
#pragma unroll
      for (int h=0; h<2; h++)
        ldsm_x4(a[h], abase + (wm*32 + h*16 + (lane&15))*ROWB2
                             + (kk + ((lane>>4)<<3))*2);
#pragma unroll
      for (int p=0; p<NP; p++)
        ldsm_x4(b[p], bbase + (wn*(NT8*8) + p*16 + ((lane>>4)&1)*8 + (lane&7))*ROWB2
                             + (kk + (((lane>>3)&1)<<3))*2);
#pragma unroll
      for (int mi=0; mi<2; mi++)
#pragma unroll
        for (int p=0; p<NP; p++){
          mma16816h(acc[mi][2*p+0], a[mi], &b[p][0]);
          mma16816h(acc[mi][2*p+1], a[mi], &b[p][2]);
        }
    }
  }

#pragma unroll
  for (int mi=0; mi<2; mi++){
#pragma unroll
    for (int ni=0; ni<NT8; ni++){
      int mrow = m0 + wm*32 + mi*16 + (lane>>2);
      int ncol = n0 + wn*(NT8*8) + ni*8 + (lane&3)*2;
#pragma unroll
      for (int hh=0; hh<2; hh++){
        int m = mrow + hh*8;
        float v0 = acc[mi][ni][2*hh+0]*cscale;
        float v1 = acc[mi][ni][2*hh+1]*cscale;
        if (SPLIT_N){
          int nl = ncol & 1023;
          const float* bs = (ncol >= 1024) ? bias1 : bias0;
          v0 += bs[nl]; v1 += bs[nl+1];
          float* dst = Cf + ((ncol >= 1024) ? 2097152LL : 0LL) + (ll)m*1024 + nl;
          *(float2*)dst = make_float2(v0,v1);
        } else {
          *(float2*)(Cf + (ll)m*ldc + ncol) = make_float2(v0,v1);
        }
      }
    }
  }
}

// ---------------- fused flash attention (fp16, 128-thread CTAs, occ 2) ----------------
// CTA: 64 q-rows (4 warps x 16 rows). smem: Q(17408) + 2 K slots + 1 V buffer.
// Pipeline invariant entering chunk nc, kc0: pending groups {K(2nc), K(2nc+1)}.
//  kc0: wait K(2nc); sync; issue V(nc); QK half0 (slot 0 parity).
//  kc1: wait K(2nc+1); sync; issue K(2nc+2); QK half1.
//  pre-PV: wait V(nc); sync; issue K(2nc+3); PV on single V buffer.
#define QROWB 272     // 256B (128 fp16) + 16 pad
#define KROWB 144     // 128B (64 fp16) + 16 pad
#define KSLOT 18432   // 128*144
#define VROWB 272
#define OFF_K  17408                  // Q = 64*272
#define OFF_V  54272                  // OFF_K + 2*KSLOT
#define FSMEM  89088                  // OFF_V + 128*272

DEVFN void flash_issueK(uint32_t sb, const __half* Kb, int g, int tid){
  const __half* Kc = Kb + (ll)((g>>1)*128)*128 + (g&1)*64;
  uint32_t kb = sb + OFF_K + (g&1)*KSLOT;
#pragma unroll
  for (int i=0;i<8;i++){
    int f = tid + i*128;
    int r = f>>3, q = f&7;
    cp_async16(kb + r*KROWB + q*16, (const char*)(Kc + (ll)r*128) + q*16);
  }
}
DEVFN void flash_issueV(uint32_t sb, const __half* Vc, int tid){
#pragma unroll
  for (int i=0;i<16;i++){
    int f = tid + i*128;
    int r = f>>4, c = f&15;
    cp_async16(sb + OFF_V + r*VROWB + c*16, (const char*)(Vc + (ll)r*1024) + c*16);
  }
}

__global__ __launch_bounds__(128, 2)
void flash_attn(const __half* __restrict__ qp,
                const __half* __restrict__ kp,
                const __half* __restrict__ vtp,
                __half* __restrict__ aop)
{
  extern __shared__ char smem[];
  const uint32_t sb = smem_u32(smem);
  const int tid = threadIdx.x, wid = tid>>5, lane = tid&31;
  const int z = blockIdx.y, b = z>>4, h = z&15;
  const int s0 = blockIdx.x*64;
  const __half* Qb = qp + ((ll)z*1024 + s0)*128;
  const __half* Kb = kp + (ll)(z>>2)*1024*128;
  const __half* Vb = vtp + (ll)(z>>2)*128*1024;

  // Q tile (64 x 128 fp16) rides with K(0) in group 0
#pragma unroll
  for (int i=0;i<8;i++){
    int f = tid + i*128;
    int r = f>>4, c = f&15;
    cp_async16(sb + r*QROWB + c*16, (const char*)(Qb + (ll)r*128) + c*16);
  }
  flash_issueK(sb, Kb, 0, tid); CP_COMMIT();   // group: Q + K(0)
  flash_issueK(sb, Kb, 1, tid); CP_COMMIT();   // group: K(1)

  float m0=-1e30f, m1=-1e30f, l0=0.f, l1=0.f;
  float o[16][4];
#pragma unroll
  for (int ni=0;ni<16;ni++){ o[ni][0]=0.f;o[ni][1]=0.f;o[ni][2]=0.f;o[ni][3]=0.f; }

#pragma unroll 1
  for (int nc=0; nc<8; nc++){
    float acc[16][4];
#pragma unroll
    for (int ni=0;ni<16;ni++){ acc[ni][0]=0.f;acc[ni][1]=0.f;acc[ni][2]=0.f;acc[ni][3]=0.f; }

#pragma unroll
    for (int kc=0; kc<2; kc++){
      const int g = nc*2 + kc;
      cp_waitg<1>();          // K(g) ready
      __syncthreads();        // kc0: all warps past PV(nc-1) -> V overwrite safe
                              // kc1: all warps done QK(g-1)... -> K slot reuse safe
      if (kc == 0){ flash_issueV(sb, Vb + nc*128, tid); CP_COMMIT(); }
      else        { if (g+1 < 16) flash_issueK(sb, Kb, g+1, tid); CP_COMMIT(); }
      const uint32_t kb = sb + OFF_K + (g&1)*KSLOT;
      const int qc = kc*64;
#pragma unroll
      for (int kk=0; kk<64; kk+=16){
        uint32_t a[4];
        ldsm_x4(a, sb + (wid*16 + (lane&15))*QROWB + (qc + kk + ((lane>>4)<<3))*2);
        uint32_t bf[8][4];
#pragma unroll
        for (int p=0;p<8;p++)
          ldsm_x4(bf[p], kb + (p*16 + ((lane>>4)&1)*8 + (lane&7))*KROWB
                            + (kk + (((lane>>3)&1)<<3))*2);
#pragma unroll
        for (int p=0;p<8;p++){
          mma16816h(acc[2*p+0], a, &bf[p][0]);
          mma16816h(acc[2*p+1], a, &bf[p][2]);
        }
      }
    }

    // ---- online softmax (base-2; log2e folded into q scale) ----
    float cm0=-1e30f, cm1=-1e30f;
#pragma unroll
    for (int ni=0;ni<16;ni++){
      cm0 = fmaxf(cm0, fmaxf(acc[ni][0], acc[ni][1]));
      cm1 = fmaxf(cm1, fmaxf(acc[ni][2], acc[ni][3]));
    }
    cm0 = fmaxf(cm0, __shfl_xor_sync(0xffffffffu, cm0, 1));
    cm0 = fmaxf(cm0, __shfl_xor_sync(0xffffffffu, cm0, 2));
    cm1 = fmaxf(cm1, __shfl_xor_sync(0xffffffffu, cm1, 1));
    cm1 = fmaxf(cm1, __shfl_xor_sync(0xffffffffu, cm1, 2));
    float mn0 = fmaxf(m0, cm0), mn1 = fmaxf(m1, cm1);
    float sc0 = exp2f(m0 - mn0), sc1 = exp2f(m1 - mn1);
    m0 = mn0; m1 = mn1;
    float rs0=0.f, rs1=0.f;
#pragma unroll
    for (int ni=0;ni<16;ni++){
      acc[ni][0]=exp2f(acc[ni][0]-m0); acc[ni][1]=exp2f(acc[ni][1]-m0);
      acc[ni][2]=exp2f(acc[ni][2]-m1); acc[ni][3]=exp2f(acc[ni][3]-m1);
      rs0 += acc[ni][0]+acc[ni][1];
      rs1 += acc[ni][2]+acc[ni][3];
    }
    rs0 += __shfl_xor_sync(0xffffffffu, rs0, 1);
    rs0 += __shfl_xor_sync(0xffffffffu, rs0, 2);
    rs1 += __shfl_xor_sync(0xffffffffu, rs1, 1);
    rs1 += __shfl_xor_sync(0xffffffffu, rs1, 2);
    l0 = l0*sc0 + rs0;
    l1 = l1*sc1 + rs1;
#pragma unroll
    for (int ni=0;ni<16;ni++){
      o[ni][0]*=sc0; o[ni][1]*=sc0; o[ni][2]*=sc1; o[ni][3]*=sc1;
    }

    // ---- PV: wait V, sync, prefetch K(2nc+3), then mma ----
    cp_waitg<1>();            // drains V(nc); K(2nc+2) may pend
    __syncthreads();          // V visible; all warps done QK on slot (2nc+1)&1
    { int g3 = nc*2+3; if (g3 < 16) flash_issueK(sb, Kb, g3, tid); CP_COMMIT(); }
#pragma unroll
    for (int kg=0; kg<8; kg++){
      uint32_t ap[4];
      ap[0] = packh2(acc[2*kg][0],   acc[2*kg][1]);
      ap[1] = packh2(acc[2*kg][2],   acc[2*kg][3]);
      ap[2] = packh2(acc[2*kg+1][0], acc[2*kg+1][1]);
      ap[3] = packh2(acc[2*kg+1][2], acc[2*kg+1][3]);
#pragma unroll
      for (int p=0;p<8;p++){
        uint32_t bh[4];
        ldsm_x4(bh, sb + OFF_V + (p*16 + ((lane>>4)&1)*8 + (lane&7))*VROWB
                               + (kg*16 + (((lane>>3)&1)<<3))*2);
        mma16816h(o[2*p+0], ap, &bh[0]);
        mma16816h(o[2*p+1], ap, &bh[2]);
      }
    }
  }

  // ---- epilogue: normalize -> fp16 aop ----
  const float inv0 = 1.f/l0, inv1 = 1.f/l1;
  const int qrow0 = s0 + wid*16 + (lane>>2);
  const ll rb0 = ((ll)(b*1024 + qrow0))*2048 + h*128;
  const ll rb1 = rb0 + 8LL*2048;
#pragma unroll
  for (int ni=0;ni<16;ni++){
    int col = ni*8 + (lane&3)*2;
    *(uint32_t*)(aop + rb0 + col) = packh2(o[ni][0]*inv0, o[ni][1]*inv0);
    *(uint32_t*)(aop + rb1 + col) = packh2(o[ni][2]*inv1, o[ni][3]*inv1);
  }
}

// ---------------- merged prep: RMSNorm+RoPE (fp16 q/k) | V transpose ----------------
__global__ __launch_bounds__(256)
void prep_qkv(const float* __restrict__ comb,
              const float* __restrict__ cosT, const float* __restrict__ sinT,
              const float* __restrict__ gql, const float* __restrict__ gkl,
              const float* __restrict__ gqg, const float* __restrict__ gkg,
              __half* __restrict__ qp, __half* __restrict__ kp,
              __half* __restrict__ vp)
{
  __shared__ float shbuf[32*33];
  const int t = threadIdx.x;

  if (blockIdx.x >= 2048){
    int b2 = blockIdx.x - 2048;
    const int s0 = (b2 & 31)*32;
    const int c0 = ((b2>>5)&7)*32;
    const int zz = b2>>8;
    const int b = zz>>1, strm = zz&1;
    float (*tt)[33] = (float(*)[33])shbuf;
    const int tx = t&31, ty = t>>5;
    const float* base = comb + (ll)strm*2048*1536;
#pragma unroll
    for (int r=0;r<32;r+=8)
      tt[ty+r][tx] = base[(ll)(b*1024 + s0+ty+r)*1536 + 1280 + c0 + tx];
    __syncthreads();
#pragma unroll
    for (int r=0;r<32;r+=8){
      int v = c0 + ty + r;
      int kh = v>>6, d = v&63;
      ll row = (ll)(b*4+kh)*128 + strm*64 + d;
      vp[row*1024 + s0 + tx] = __float2half_rn(tt[tx][ty+r]);
    }
    return;
  }

  const int bs = blockIdx.x;
  const int b = bs >> 10, s = bs & 1023;
  const float* rl = comb + (ll)bs*1536;
  const float* rg = rl + (ll)2048*1536;

  float sql=0.f, sqg=0.f;
#pragma unroll
  for (int i=t;i<1024;i+=256){ float x=rl[i]; sql+=x*x; float y=rg[i]; sqg+=y*y; }
  float xk=rl[1024+t], yk=rg[1024+t];
  float skl = xk*xk, skg = yk*yk;

  float4* red = (float4*)shbuf;
  float4 v4 = make_float4(sql,sqg,skl,skg);
#pragma unroll
  for (int off=16;off;off>>=1){
    v4.x += __shfl_xor_sync(0xffffffffu, v4.x, off);
    v4.y += __shfl_xor_sync(0xffffffffu, v4.y, off);
    v4.z += __shfl_xor_sync(0xffffffffu, v4.z, off);
    v4.w += __shfl_xor_sync(0xffffffffu, v4.w, off);
  }
  const int w = t>>5, l = t&31;
  if (!l) red[w]=v4;
  __syncthreads();
  if (t==0){
    float4 a = red[0];
    for (int i=1;i<8;i++){ a.x+=red[i].x; a.y+=red[i].y; a.z+=red[i].z; a.w+=red[i].w; }
    red[0]=a;
  }
  __syncthreads();
  float4 tot = red[0];
  const float QF = 0.125f * 1.4426950408889634f;
  const float rql = rsqrtf(tot.x*(1.f/1024.f)+1e-5f) * QF;
  const float rqg = rsqrtf(tot.y*(1.f/1024.f)+1e-5f) * QF;
  const float rkl = rsqrtf(tot.z*(1.f/256.f)+1e-5f);
  const float rkg = rsqrtf(tot.w*(1.f/256.f)+1e-5f);

#pragma unroll
  for (int pp=t; pp<512; pp+=256){
    int h = pp>>5, p = pp&31;
    float c = cosT[s*32+p], sn = sinT[s*32+p];
    int d0 = h*64 + 2*p;
    ll base = (((ll)(b*16+h))*1024 + s)*128;
    float x0 = rl[d0]*rql*gql[d0];
    float x1 = rl[d0+1]*rql*gql[d0+1];
    float y0 = rg[d0]*rqg*gqg[d0];
    float y1 = rg[d0+1]*rqg*gqg[d0+1];
    *(uint32_t*)(qp+base+2*p)    = packh2(x0*c - x1*sn, x0*sn + x1*c);
    *(uint32_t*)(qp+base+64+2*p) = packh2(y0*c - y1*sn, y0*sn + y1*c);
  }
  if (t < 128){
    int kh = t>>5, p = t&31;
    float c = cosT[s*32+p], sn = sinT[s*32+p];
    int gd = kh*64 + 2*p;
    ll base = (((ll)(b*4+kh))*1024 + s)*128;
    float x0 = rl[1024+gd]*rkl*gkl[gd];
    float x1 = rl[1024+gd+1]*rkl*gkl[gd+1];
    float y0 = rg[1024+gd]*rkg*gkg[gd];
    float y1 = rg[1024+gd+1]*rkg*gkg[gd+1];
    *(uint32_t*)(kp+base+2*p)    = packh2(x0*c - x1*sn, x0*sn + x1*c);
    *(uint32_t*)(kp+base+64+2*p) = packh2(y0*c - y1*sn, y0*sn + y1*c);
  }
}

// ---------------- final RMSNorm -> d_out ----------------
__global__ __launch_bounds__(256)
void rmsnorm_out(const float* __restrict__ y, const float* __restrict__ glc,
                 const float* __restrict__ ggc, float* __restrict__ out)
{
  const int row = blockIdx.x;
  const float* g = (row < 2048) ? glc : ggc;
  const float* r = y + (ll)row*1024;
  float* o = out + (ll)row*1024;
  const int t = threadIdx.x;
  float4 v = ((const float4*)r)[t];
  float ss = v.x*v.x + v.y*v.y + v.z*v.z + v.w*v.w;
  __shared__ float sm[8];
#pragma unroll
  for (int o2=16;o2;o2>>=1) ss += __shfl_xor_sync(0xffffffffu,ss,o2);
  const int w=t>>5, l=t&31;
  if (!l) sm[w]=ss;
  __syncthreads();
  ss = sm[0]+sm[1]+sm[2]+sm[3]+sm[4]+sm[5]+sm[6]+sm[7];
  const float rsq = rsqrtf(ss*(1.f/1024.f)+1e-5f);
  float4 gv = ((const float4*)g)[t];
  float4 ov = make_float4(v.x*rsq*gv.x, v.y*rsq*gv.y, v.z*rsq*gv.z, v.w*rsq*gv.w);
  ((float4*)o)[t]=ov;
}

// ---------------- launch ----------------
extern "C" void kernel_launch(void* const* d_in, const int* in_sizes, int n_in,
                              void* d_out, int out_size)
{
  (void)in_sizes; (void)n_in; (void)out_size;
  const float* local_c  = (const float*)d_in[0];
  const float* global_c = (const float*)d_in[1];
  const float* fcos     = (const float*)d_in[2];
  const float* fsin     = (const float*)d_in[3];
  const float* W_lc     = (const float*)d_in[4];
  const float* W_gc     = (const float*)d_in[5];
  const float* g_q_lc   = (const float*)d_in[6];
  const float* g_k_lc   = (const float*)d_in[7];
  const float* g_q_gc   = (const float*)d_in[8];
  const float* g_k_gc   = (const float*)d_in[9];
  const float* W_local  = (const float*)d_in[10];
  const float* b_local  = (const float*)d_in[11];
  const float* g_lc_out = (const float*)d_in[12];
  const float* W_global = (const float*)d_in[13];
  const float* b_global = (const float*)d_in[14];
  const float* g_gc_out = (const float*)d_in[15];

  __half *xp,*wq,*wp,*qp,*kp,*vtp,*aop;
  float *comb,*yy;
  cudaGetSymbolAddress((void**)&xp,  g_x_pack);
  cudaGetSymbolAddress((void**)&wq,  g_wqkv_pack);
  cudaGetSymbolAddress((void**)&wp,  g_wpr_pack);
  cudaGetSymbolAddress((void**)&comb, g_comb);
  cudaGetSymbolAddress((void**)&qp,  g_q);
  cudaGetSymbolAddress((void**)&kp,  g_k);
  cudaGetSymbolAddress((void**)&vtp, g_vT);
  cudaGetSymbolAddress((void**)&aop, g_ao);
  cudaGetSymbolAddress((void**)&yy,  g_yy);

  const int SM_QKV = 3*((128+96)*144);   // 96768
  const int SM_OUT = 3*((128+128)*144);  // 110592
  static int attr_done = 0;
  if (!attr_done){
    cudaFuncSetAttribute((const void*)gemm_mma<false,6,2>,
                         cudaFuncAttributeMaxDynamicSharedMemorySize, SM_QKV);
    cudaFuncSetAttribute((const void*)gemm_mma<true,8,1>,
                         cudaFuncAttributeMaxDynamicSharedMemorySize, SM_OUT);
    cudaFuncSetAttribute((const void*)flash_attn,
                         cudaFuncAttributeMaxDynamicSharedMemorySize, FSMEM);
    attr_done = 1;
  }

  // 0) operand packs
  packAll<<<5632,256>>>(local_c, global_c, W_lc, W_gc, W_local, W_global, xp, wq, wp);

  // 1) QKV projections, fp16 2-term (x exact split, W fp16), N-tile 96
  gemm_mma<false,6,2><<<dim3(16,16,2),256,SM_QKV>>>(xp, wq, comb, nullptr, nullptr,
     1024, 4, 2048, 1024, 1536, 2048LL*2048, 1536LL*1024, 2048LL*1536, 1.f);

  // 2) merged rmsnorm+rope (fp16 q/k) + V transpose (fp16)
  prep_qkv<<<3072,256>>>(comb, fcos, fsin, g_q_lc, g_k_lc, g_q_gc, g_k_gc, qp, kp, vtp);

  // 3) fused attention, 128-thread CTAs, occ 2
  flash_attn<<<dim3(16,32),128,FSMEM>>>(qp, kp, vtp, aop);

  // 4) merged output projections, fp16 1-term + bias  (M=2048,N=2048,K=2048,lgn1=5)
  gemm_mma<true,8,1><<<dim3(16,16,1),256,SM_OUT>>>(aop, wp, yy, b_local, b_global,
     2048, 5, 2048, 2048, 1024, 0,0,0, 1.f);

  // 5) final rmsnorm -> d_out
  rmsnorm_out<<<4096,256>>>(yy, g_lc_out, g_gc_out, (float*)d_out);
}